// round 11
// baseline (speedup 1.0000x reference)
#include <cuda_runtime.h>
#include <cuda_bf16.h>
#include <math.h>
#include <stdint.h>

#define RB 4
#define CC 256
#define HWSZ 4096
#define OC2 18
#define PW 68
#define PHW 4624            // 68*68
#define PBASE 138           // 2*68 + 2

// ---------------- smem layout (bytes, dynamic) ------------------------------
// phase2: A 128oc x 128ck s8: hi 16K @0, lo @16384. B 128px x 128ck s8 hi/lo.
// phase1 (bf16) reuses: A_off 32x64 bf16 hi@SM_A lo@SM_ALO (4KB each),
//                       B 128x64 bf16 hi@SM_B lo@SM_BLO (16KB each),
//                       offs f32 [32][128] reuses SM_B.
#define SM_A    0
#define SM_ALO  16384
#define SM_B    32768
#define SM_BLO  49152
#define SM_IDX  65536       // int[1152]
#define SM_WY   70144       // float[1152]
#define SM_WX   74752       // float[1152]
#define SM_SA   79360       // float[256]
#define SM_TOTAL 80384

// 128B-row swizzle
#define SW(row, colb) (((uint32_t)(row) << 7) + \
    ((uint32_t)(colb) ^ (((uint32_t)(row) & 7) << 4)))

// ---------------- scratch ----------------------------------------------------
__device__ float g_padA[4734976];
__device__ float g_padB[4734976];
// int8 weights: [r][kb18][oc256][j128], c = (kb&1)*128 + j, kk = kb>>1
__device__ __align__(16) int8_t g_wh8[2359296];
__device__ __align__(16) int8_t g_wl8[2359296];
__device__ float g_sa[1024];          // per-oc weight scales [r][oc]
__device__ float g_scaleB[8];         // per-layer activation max
// offset-conv weights bf16: [r][kb36][ocp32][j64]
__device__ __align__(16) __nv_bfloat16 g_owhi[294912];
__device__ __align__(16) __nv_bfloat16 g_owlo[294912];

// ---------------- PTX helpers ----------------------------------------------
static __device__ __forceinline__ uint32_t smem_u32(const void* p) {
    uint32_t a;
    asm("{ .reg .u64 t; cvta.to.shared.u64 t, %1; cvt.u32.u64 %0, t; }" : "=r"(a) : "l"(p));
    return a;
}

#define LDSM4(r, a) \
    asm volatile("ldmatrix.sync.aligned.m8n8.x4.shared.b16 {%0,%1,%2,%3}, [%4];" \
                 : "=r"((r)[0]), "=r"((r)[1]), "=r"((r)[2]), "=r"((r)[3]) : "r"(a))

#define MMA16816(c, a, b0, b1) \
    asm volatile("mma.sync.aligned.m16n8k16.row.col.f32.bf16.bf16.f32 " \
                 "{%0,%1,%2,%3}, {%4,%5,%6,%7}, {%8,%9}, {%0,%1,%2,%3};" \
                 : "+f"((c)[0]), "+f"((c)[1]), "+f"((c)[2]), "+f"((c)[3]) \
                 : "r"((a)[0]), "r"((a)[1]), "r"((a)[2]), "r"((a)[3]), \
                   "r"(b0), "r"(b1))

#define IMMA16832(c, a, b0, b1) \
    asm volatile("mma.sync.aligned.m16n8k32.row.col.s32.s8.s8.s32 " \
                 "{%0,%1,%2,%3}, {%4,%5,%6,%7}, {%8,%9}, {%0,%1,%2,%3};" \
                 : "+r"((c)[0]), "+r"((c)[1]), "+r"((c)[2]), "+r"((c)[3]) \
                 : "r"((a)[0]), "r"((a)[1]), "r"((a)[2]), "r"((a)[3]), \
                   "r"(b0), "r"(b1))

#define CP16(dst, src) \
    asm volatile("cp.async.cg.shared.global [%0], [%1], 16;" :: "r"(dst), "l"(src))
#define CP_COMMIT() asm volatile("cp.async.commit_group;")
#define CP_WAIT0()  asm volatile("cp.async.wait_group 0;")

// ---------------- prep kernels ----------------------------------------------
__global__ void init_scales_kernel() {
    if (threadIdx.x < 8) g_scaleB[threadIdx.x] = 0.f;
}

__global__ void pad_input_kernel(const float* __restrict__ x,
                                 float* __restrict__ pA, float* __restrict__ pB) {
    __shared__ float red[256];
    int i = blockIdx.x * 256 + threadIdx.x;
    float m = 0.f;
    if (i < 4734976) {
        int plane = i / PHW, rem = i - plane * PHW;
        int h = rem / PW - 2, w = rem % PW - 2;
        float v = 0.f;
        if (h >= 0 && h < 64 && w >= 0 && w < 64) v = x[plane * HWSZ + h * 64 + w];
        pA[i] = v;
        pB[i] = 0.f;
        m = fabsf(v);
    }
    red[threadIdx.x] = m;
    __syncthreads();
    for (int s = 128; s; s >>= 1) {
        if (threadIdx.x < s) red[threadIdx.x] = fmaxf(red[threadIdx.x], red[threadIdx.x + s]);
        __syncthreads();
    }
    if (threadIdx.x == 0)
        atomicMax((unsigned int*)&g_scaleB[0], __float_as_uint(red[0]));
}

// per-(r,oc) row quantization of main weights
__global__ void prep_w8_kernel(const float* __restrict__ w,
                               int8_t* __restrict__ wh, int8_t* __restrict__ wl,
                               float* __restrict__ sa) {
    __shared__ float red[256];
    int blk = blockIdx.x;          // r*256 + oc
    int r = blk >> 8, oc = blk & 255;
    const float* wrow = w + (size_t)blk * 2304;
    float m = 0.f;
    for (int i = threadIdx.x; i < 2304; i += 256) m = fmaxf(m, fabsf(wrow[i]));
    red[threadIdx.x] = m;
    __syncthreads();
    for (int s = 128; s; s >>= 1) {
        if (threadIdx.x < s) red[threadIdx.x] = fmaxf(red[threadIdx.x], red[threadIdx.x + s]);
        __syncthreads();
    }
    float rm = fmaxf(red[0], 1e-20f);
    if (threadIdx.x == 0) sa[blk] = rm * (1.0f / 127.0f);
    float inv = 127.0f / rm;
    for (int i = threadIdx.x; i < 2304; i += 256) {
        int c = i / 9, kk = i - c * 9;
        float q = wrow[i] * inv;
        float hf = rintf(q);
        int hi = (int)hf;
        int lo = __float2int_rn((q - hf) * 128.f);
        int kb = kk * 2 + (c >> 7), j = c & 127;
        size_t dst = (((size_t)r * 18 + kb) * 256 + oc) * 128 + j;
        wh[dst] = (int8_t)hi;
        wl[dst] = (int8_t)lo;
    }
}

__global__ void prep_offw_kernel(const float* __restrict__ offw,
                                 __nv_bfloat16* __restrict__ owhi,
                                 __nv_bfloat16* __restrict__ owlo) {
    int idx = blockIdx.x * 256 + threadIdx.x;
    if (idx >= 294912) return;
    int r = idx / 73728;
    int rem = idx - r * 73728;
    int kb = rem >> 11;
    int rem2 = rem & 2047;
    int ocp = rem2 >> 6;
    int j = rem2 & 63;
    int kk = kb >> 2;
    int c = ((kb & 3) << 6) + j;
    float v = (ocp < OC2) ? offw[((r * OC2 + ocp) * 256 + c) * 9 + kk] : 0.f;
    __nv_bfloat16 h = __float2bfloat16_rn(v);
    owhi[idx] = h;
    owlo[idx] = __float2bfloat16_rn(v - __bfloat162float(h));
}

// ---------------- helpers ----------------------------------------------------
static __device__ __forceinline__ void cvt_pair(float v0, float v1,
        uint32_t& hp, uint32_t& lp) {
    __nv_bfloat162 h2, l2;
    h2.x = __float2bfloat16_rn(v0);
    h2.y = __float2bfloat16_rn(v1);
    l2.x = __float2bfloat16_rn(v0 - __bfloat162float(h2.x));
    l2.y = __float2bfloat16_rn(v1 - __bfloat162float(h2.y));
    hp = *(uint32_t*)&h2;
    lp = *(uint32_t*)&l2;
}

// ---------------- fused layer kernel ----------------------------------------
// grid = 128 CTAs (4 b x 32 px-tiles of 128), 256 threads / 8 warps.
// Phase1: bf16 offset GEMM (32x128). Phase2: int8 deform GEMM, 2 oc-halves
// serially, each 128oc x 128px, warp tile 32x64 (4m x 2n).
__global__ __launch_bounds__(256, 1) void fused_layer_kernel(
    const float* __restrict__ xpad,
    const __nv_bfloat16* __restrict__ owhi, const __nv_bfloat16* __restrict__ owlo,
    const float* __restrict__ offbias,
    const int8_t* __restrict__ wh8, const int8_t* __restrict__ wl8,
    const float* __restrict__ sa_base, float* scaleB, int r,
    float* __restrict__ outp, int pad_out)
{
    extern __shared__ char smem[];
    uint32_t sb = smem_u32(smem);
    int tid = threadIdx.x;
    int lane = tid & 31;
    int wid = tid >> 5;
    int b = blockIdx.x >> 5;
    int px0 = (blockIdx.x & 31) << 7;

    int px = tid & 127;
    int chalf = tid >> 7;            // 0/1
    int hpx = (px0 + px) >> 6;
    int wpx = (px0 + px) & 63;

    // preload per-oc weight scales
    ((float*)(smem + SM_SA))[tid] = sa_base[tid];

    // ================= PHASE 1: bf16 offset conv GEMM (D_off[32][128]) =====
    float acc1[2][2][4];
#pragma unroll
    for (int mi = 0; mi < 2; ++mi)
#pragma unroll
        for (int nj = 0; nj < 2; ++nj)
#pragma unroll
            for (int q = 0; q < 4; ++q) acc1[mi][nj][q] = 0.f;

    int n_base1 = wid << 4;

    for (int kb = 0; kb < 36; ++kb) {
        int kk = kb >> 2;
        if (kb) __syncthreads();

        // stage A_off hi/lo (32x64 bf16, 4KB each)
        {
            int row = tid >> 3, seg = tid & 7;
            uint32_t o = SW(row, seg << 4);
            *(uint4*)(smem + SM_A + o) =
                ((const uint4*)(owhi + ((size_t)kb << 11)))[tid];
            *(uint4*)(smem + SM_ALO + o) =
                ((const uint4*)(owlo + ((size_t)kb << 11)))[tid];
        }
        // stage B im2col bf16: [128px][64ck], thread: 32 channels
        {
            const float* xb = xpad + ((size_t)(b * 256) + ((kb & 3) << 6) + (chalf << 5)) * PHW
                            + (hpx + kk / 3 + 1) * PW + (wpx + kk % 3 + 1);
#pragma unroll
            for (int ch = 0; ch < 4; ++ch) {
                uint32_t hp[4], lp[4];
#pragma unroll
                for (int jj = 0; jj < 4; ++jj) {
                    float v0 = xb[(size_t)(ch * 8 + jj * 2) * PHW];
                    float v1 = xb[(size_t)(ch * 8 + jj * 2 + 1) * PHW];
                    cvt_pair(v0, v1, hp[jj], lp[jj]);
                }
                uint32_t o = SW(px, (chalf << 6) + (ch << 4));
                *(uint4*)(smem + SM_B + o) = make_uint4(hp[0], hp[1], hp[2], hp[3]);
                *(uint4*)(smem + SM_BLO + o) = make_uint4(lp[0], lp[1], lp[2], lp[3]);
            }
        }
        __syncthreads();

#pragma unroll
        for (int ks = 0; ks < 4; ++ks) {
            uint32_t a1[2][4], bh[4], bl[4];
            int brow0 = n_base1 + ((lane >> 4) << 3) + (lane & 7);
            uint32_t bcolb = (uint32_t)((ks << 5) + (((lane >> 3) & 1) << 4));
            LDSM4(bh, sb + SM_B + SW(brow0, bcolb));
            LDSM4(bl, sb + SM_BLO + SW(brow0, bcolb));
            int arow0 = lane & 15;
            uint32_t acolb = (uint32_t)((ks << 5) + ((lane >> 4) << 4));
#pragma unroll
            for (int mi = 0; mi < 2; ++mi)
                LDSM4(a1[mi], sb + SM_ALO + SW(arow0 + (mi << 4), acolb));
#pragma unroll
            for (int mi = 0; mi < 2; ++mi)
#pragma unroll
                for (int nj = 0; nj < 2; ++nj)
                    MMA16816(acc1[mi][nj], a1[mi], bh[nj * 2], bh[nj * 2 + 1]);
#pragma unroll
            for (int mi = 0; mi < 2; ++mi)
                LDSM4(a1[mi], sb + SM_A + SW(arow0 + (mi << 4), acolb));
#pragma unroll
            for (int mi = 0; mi < 2; ++mi)
#pragma unroll
                for (int nj = 0; nj < 2; ++nj) {
                    MMA16816(acc1[mi][nj], a1[mi], bh[nj * 2], bh[nj * 2 + 1]);
                    MMA16816(acc1[mi][nj], a1[mi], bl[nj * 2], bl[nj * 2 + 1]);
                }
        }
    }
    __syncthreads();

    // offsets to smem (reuse SM_B): offs[32][128] f32
    {
        float* offs = (float*)(smem + SM_B);
#pragma unroll
        for (int mi = 0; mi < 2; ++mi)
#pragma unroll
            for (int nj = 0; nj < 2; ++nj) {
                int ocp = (mi << 4) + (lane >> 2);
                int pc = (wid << 4) + (nj << 3) + ((lane & 3) << 1);
                offs[ocp * 128 + pc] = acc1[mi][nj][0];
                offs[ocp * 128 + pc + 1] = acc1[mi][nj][1];
                offs[(ocp + 8) * 128 + pc] = acc1[mi][nj][2];
                offs[(ocp + 8) * 128 + pc + 1] = acc1[mi][nj][3];
            }
    }
    __syncthreads();

    // bilinear metadata
    {
        const float* offs = (const float*)(smem + SM_B);
        int* sIdx = (int*)(smem + SM_IDX);
        float* sWy = (float*)(smem + SM_WY);
        float* sWx = (float*)(smem + SM_WX);
        for (int i = tid; i < 1152; i += 256) {
            int kk = i >> 7;
            int p = i & 127;
            int pix = px0 + p;
            int h = pix >> 6;
            int w = pix & 63;
            float dy = offs[((2 * kk) << 7) + p] + offbias[2 * kk];
            float dx = offs[((2 * kk + 1) << 7) + p] + offbias[2 * kk + 1];
            float py = fminf(fmaxf((float)(h + kk / 3 - 1) + dy, -1.5f), 64.5f);
            float pxx = fminf(fmaxf((float)(w + kk % 3 - 1) + dx, -1.5f), 64.5f);
            float y0f = floorf(py), x0f = floorf(pxx);
            sIdx[i] = ((int)y0f + 2) * PW + ((int)x0f + 2);
            sWy[i] = py - y0f;
            sWx[i] = pxx - x0f;
        }
    }
    __syncthreads();

    // ================= PHASE 2: int8 deform GEMM, 2 oc-halves =============
    float t = fmaxf(scaleB[r], 1e-20f);
    float inv = 127.0f / t;
    float tsc = t * (1.0f / 127.0f);
    float mloc = 0.f;

    int m_base = (wid & 3) << 5;       // 0..96
    int n_base = (wid >> 2) << 6;      // 0 or 64

    int plane = pad_out ? PHW : HWSZ;
    int ostride = pad_out ? PW : 64;
    int obase = pad_out ? PBASE : 0;

    for (int oh = 0; oh < 2; ++oh) {
        int acch[2][8][4], accm[2][8][4];
#pragma unroll
        for (int mi = 0; mi < 2; ++mi)
#pragma unroll
            for (int nj = 0; nj < 8; ++nj)
#pragma unroll
                for (int q = 0; q < 4; ++q) { acch[mi][nj][q] = 0; accm[mi][nj][q] = 0; }

        for (int kb = 0; kb < 18; ++kb) {
            int kk = kb >> 1;
            int c0 = (kb & 1) << 7;
            __syncthreads();   // smem tiles free (prior mma / phase1 done)

            // stage A s8 hi/lo via cp.async: 128 rows x 128 B each
            {
                const char* ah = (const char*)wh8 + ((size_t)kb << 15) + ((size_t)oh << 14);
                const char* al = (const char*)wl8 + ((size_t)kb << 15) + ((size_t)oh << 14);
#pragma unroll
                for (int tt = 0; tt < 4; ++tt) {
                    int i = tid + (tt << 8);
                    int row = i >> 3, seg = i & 7;
                    uint32_t o = SW(row, seg << 4);
                    CP16(sb + SM_A + o, ah + ((size_t)i << 4));
                    CP16(sb + SM_ALO + o, al + ((size_t)i << 4));
                }
                CP_COMMIT();
            }

            // stage B: gather + interp + quantize, 64 channels per thread
            {
                int mi_ = kk * 128 + px;
                int idx0 = ((const int*)(smem + SM_IDX))[mi_];
                float wy = ((const float*)(smem + SM_WY))[mi_];
                float wx = ((const float*)(smem + SM_WX))[mi_];
                float w01 = (1.f - wy) * wx;
                float w00 = (1.f - wy) - w01;
                float w11 = wy * wx;
                float w10 = wy - w11;
                const float* xb = xpad + ((size_t)(b * 256) + c0 + (chalf << 6)) * PHW + idx0;
#pragma unroll
                for (int t4 = 0; t4 < 4; ++t4) {
                    uint32_t hw4[4], lw4[4];
#pragma unroll
                    for (int g = 0; g < 4; ++g) {
                        uint32_t hp = 0, lp = 0;
#pragma unroll
                        for (int u = 0; u < 4; ++u) {
                            int ch = t4 * 16 + g * 4 + u;
                            const float* p0 = xb + (size_t)ch * PHW;
                            float v = fmaf(w11, p0[PW + 1], fmaf(w10, p0[PW],
                                      fmaf(w01, p0[1], w00 * p0[0])));
                            float q = v * inv;
                            float hf = rintf(q);
                            int hi = (int)hf;
                            int lo = __float2int_rn((q - hf) * 128.f);
                            hp |= (uint32_t)(hi & 255) << (u * 8);
                            lp |= (uint32_t)(lo & 255) << (u * 8);
                        }
                        hw4[g] = hp;
                        lw4[g] = lp;
                    }
                    uint32_t o = SW(px, (chalf << 6) + (t4 << 4));
                    *(uint4*)(smem + SM_B + o) = make_uint4(hw4[0], hw4[1], hw4[2], hw4[3]);
                    *(uint4*)(smem + SM_BLO + o) = make_uint4(lw4[0], lw4[1], lw4[2], lw4[3]);
                }
            }
            CP_WAIT0();
            __syncthreads();

            // mma: 4 k32-steps
#pragma unroll
            for (int ks = 0; ks < 4; ++ks) {
                uint32_t bh[4][4], a2[2][4];
                int brow0 = n_base + ((lane >> 4) << 3) + (lane & 7);
                uint32_t bcolb = (uint32_t)((ks << 5) + (((lane >> 3) & 1) << 4));
                int arow0 = m_base + (lane & 15);
                uint32_t acolb = (uint32_t)((ks << 5) + ((lane >> 4) << 4));
#pragma unroll
                for (int np = 0; np < 4; ++np)
                    LDSM4(bh[np], sb + SM_B + SW(brow0 + (np << 4), bcolb));
#pragma unroll
                for (int mi = 0; mi < 2; ++mi)
                    LDSM4(a2[mi], sb + SM_ALO + SW(arow0 + (mi << 4), acolb));   // A lo
#pragma unroll
                for (int mi = 0; mi < 2; ++mi)
#pragma unroll
                    for (int nj = 0; nj < 8; ++nj)
                        IMMA16832(accm[mi][nj], a2[mi], bh[nj >> 1][(nj & 1) * 2],
                                  bh[nj >> 1][(nj & 1) * 2 + 1]);
#pragma unroll
                for (int mi = 0; mi < 2; ++mi)
                    LDSM4(a2[mi], sb + SM_A + SW(arow0 + (mi << 4), acolb));     // A hi
#pragma unroll
                for (int mi = 0; mi < 2; ++mi)
#pragma unroll
                    for (int nj = 0; nj < 8; ++nj)
                        IMMA16832(acch[mi][nj], a2[mi], bh[nj >> 1][(nj & 1) * 2],
                                  bh[nj >> 1][(nj & 1) * 2 + 1]);
#pragma unroll
                for (int np = 0; np < 4; ++np)
                    LDSM4(bh[np], sb + SM_BLO + SW(brow0 + (np << 4), bcolb));   // B lo
#pragma unroll
                for (int mi = 0; mi < 2; ++mi)
#pragma unroll
                    for (int nj = 0; nj < 8; ++nj)
                        IMMA16832(accm[mi][nj], a2[mi], bh[nj >> 1][(nj & 1) * 2],
                                  bh[nj >> 1][(nj & 1) * 2 + 1]);
            }
        }

        // epilogue for this oc-half
        const float* ssa = (const float*)(smem + SM_SA);
#pragma unroll
        for (int mi = 0; mi < 2; ++mi) {
#pragma unroll
            for (int nj = 0; nj < 8; ++nj) {
                int row = (oh << 7) + m_base + (mi << 4) + (lane >> 2);
                int colp = n_base + (nj << 3) + ((lane & 3) << 1);
                int pix = px0 + colp;
                int h = pix >> 6;
                int wv = pix & 63;
                float s0 = ssa[row] * tsc;
                float s1 = ssa[row + 8] * tsc;
                float f0 = s0 * ((float)acch[mi][nj][0] + (float)accm[mi][nj][0] * 0.0078125f);
                float f1 = s0 * ((float)acch[mi][nj][1] + (float)accm[mi][nj][1] * 0.0078125f);
                float f2 = s1 * ((float)acch[mi][nj][2] + (float)accm[mi][nj][2] * 0.0078125f);
                float f3 = s1 * ((float)acch[mi][nj][3] + (float)accm[mi][nj][3] * 0.0078125f);
                f0 = fmaxf(f0, 0.f); f1 = fmaxf(f1, 0.f);
                f2 = fmaxf(f2, 0.f); f3 = fmaxf(f3, 0.f);
                mloc = fmaxf(mloc, fmaxf(fmaxf(f0, f1), fmaxf(f2, f3)));
                float* d0 = outp + (size_t)(b * 256 + row) * plane + h * ostride + wv + obase;
                float* d1 = outp + (size_t)(b * 256 + row + 8) * plane + h * ostride + wv + obase;
                *(float2*)d0 = make_float2(f0, f1);
                *(float2*)d1 = make_float2(f2, f3);
            }
        }
    }

    // propagate activation max to next layer's scale
    __syncthreads();
#pragma unroll
    for (int off = 16; off; off >>= 1)
        mloc = fmaxf(mloc, __shfl_xor_sync(0xFFFFFFFFu, mloc, off));
    float* red = (float*)(smem + SM_IDX);
    if (lane == 0) red[wid] = mloc;
    __syncthreads();
    if (tid == 0) {
        float m = red[0];
#pragma unroll
        for (int i = 1; i < 8; ++i) m = fmaxf(m, red[i]);
        atomicMax((unsigned int*)&scaleB[r + 1], __float_as_uint(m));
    }
}

// ---------------- launch ----------------------------------------------------
extern "C" void kernel_launch(void* const* d_in, const int* in_sizes, int n_in,
                              void* d_out, int out_size) {
    (void)in_sizes; (void)n_in; (void)out_size;
    const float* x    = (const float*)d_in[0];
    const float* offw = (const float*)d_in[1];
    const float* offb = (const float*)d_in[2];
    const float* w    = (const float*)d_in[3];
    float* out = (float*)d_out;

    float *padA, *padB, *sa, *scB;
    int8_t *wh8, *wl8;
    __nv_bfloat16 *gowhi, *gowlo;
    cudaGetSymbolAddress((void**)&padA, g_padA);
    cudaGetSymbolAddress((void**)&padB, g_padB);
    cudaGetSymbolAddress((void**)&wh8, g_wh8);
    cudaGetSymbolAddress((void**)&wl8, g_wl8);
    cudaGetSymbolAddress((void**)&sa, g_sa);
    cudaGetSymbolAddress((void**)&scB, g_scaleB);
    cudaGetSymbolAddress((void**)&gowhi, g_owhi);
    cudaGetSymbolAddress((void**)&gowlo, g_owlo);

    cudaFuncSetAttribute(fused_layer_kernel,
                         cudaFuncAttributeMaxDynamicSharedMemorySize, SM_TOTAL);

    init_scales_kernel<<<1, 32>>>();
    pad_input_kernel<<<(4734976 + 255) / 256, 256>>>(x, padA, padB);
    prep_w8_kernel<<<1024, 256>>>(w, wh8, wl8, sa);
    prep_offw_kernel<<<(294912 + 255) / 256, 256>>>(offw, gowhi, gowlo);

    const float* cur = padA;
    for (int r = 0; r < RB; ++r) {
        int last = (r == 3);
        float* nxt = last ? out : ((r & 1) == 0 ? padB : padA);
        fused_layer_kernel<<<128, 256, SM_TOTAL>>>(
            cur, gowhi + (size_t)r * 73728, gowlo + (size_t)r * 73728,
            offb + r * OC2,
            wh8 + (size_t)r * 589824, wl8 + (size_t)r * 589824,
            sa + r * 256, scB, r, nxt, last ? 0 : 1);
        cur = nxt;
    }
}

// round 13
// speedup vs baseline: 1.0670x; 1.0670x over previous
#include <cuda_runtime.h>
#include <cuda_bf16.h>
#include <math.h>
#include <stdint.h>

#define RB 4
#define CC 256
#define HWSZ 4096
#define OC2 18
#define PW 68
#define PHW 4624            // 68*68
#define PBASE 138           // 2*68 + 2

// ---------------- smem layout (bytes, dynamic) ------------------------------
// phase2: A 256oc x 128ck s8 hi/lo (32KB each); B 64px x 128ck s8 hi/lo (8KB each)
// phase1 bf16 reuses SM_A/SM_ALO (32x64 bf16 = 4KB) and SM_B/SM_BLO (64x64 bf16 = 8KB)
#define SM_A    0
#define SM_ALO  32768
#define SM_B    65536
#define SM_BLO  73728
#define SM_IDX  81920       // int[576]
#define SM_WY   84224       // float[576]
#define SM_WX   86528       // float[576]
#define SM_SA   88832       // float[256]
#define SM_TOTAL 89856

// 128B-row swizzle
#define SW(row, colb) (((uint32_t)(row) << 7) + \
    ((uint32_t)(colb) ^ (((uint32_t)(row) & 7) << 4)))

// ---------------- scratch ----------------------------------------------------
__device__ float g_padA[4734976];
__device__ float g_padB[4734976];
// int8 weights: [r][kb18][oc256][j128], c = (kb&1)*128 + j, kk = kb>>1
__device__ __align__(16) int8_t g_wh8[2359296];
__device__ __align__(16) int8_t g_wl8[2359296];
__device__ float g_sa[1024];          // per-oc weight scales [r][oc]
__device__ float g_scaleB[8];         // per-layer activation max
// offset-conv weights bf16: [r][kb36][ocp32][j64]
__device__ __align__(16) __nv_bfloat16 g_owhi[294912];
__device__ __align__(16) __nv_bfloat16 g_owlo[294912];

// ---------------- PTX helpers ----------------------------------------------
static __device__ __forceinline__ uint32_t smem_u32(const void* p) {
    uint32_t a;
    asm("{ .reg .u64 t; cvta.to.shared.u64 t, %1; cvt.u32.u64 %0, t; }" : "=r"(a) : "l"(p));
    return a;
}

#define LDSM4(r, a) \
    asm volatile("ldmatrix.sync.aligned.m8n8.x4.shared.b16 {%0,%1,%2,%3}, [%4];" \
                 : "=r"((r)[0]), "=r"((r)[1]), "=r"((r)[2]), "=r"((r)[3]) : "r"(a))

#define LDSM2(r, a) \
    asm volatile("ldmatrix.sync.aligned.m8n8.x2.shared.b16 {%0,%1}, [%2];" \
                 : "=r"((r)[0]), "=r"((r)[1]) : "r"(a))

#define MMA16816(c, a, b0, b1) \
    asm volatile("mma.sync.aligned.m16n8k16.row.col.f32.bf16.bf16.f32 " \
                 "{%0,%1,%2,%3}, {%4,%5,%6,%7}, {%8,%9}, {%0,%1,%2,%3};" \
                 : "+f"((c)[0]), "+f"((c)[1]), "+f"((c)[2]), "+f"((c)[3]) \
                 : "r"((a)[0]), "r"((a)[1]), "r"((a)[2]), "r"((a)[3]), \
                   "r"(b0), "r"(b1))

#define IMMA16832(c, a, b0, b1) \
    asm volatile("mma.sync.aligned.m16n8k32.row.col.s32.s8.s8.s32 " \
                 "{%0,%1,%2,%3}, {%4,%5,%6,%7}, {%8,%9}, {%0,%1,%2,%3};" \
                 : "+r"((c)[0]), "+r"((c)[1]), "+r"((c)[2]), "+r"((c)[3]) \
                 : "r"((a)[0]), "r"((a)[1]), "r"((a)[2]), "r"((a)[3]), \
                   "r"(b0), "r"(b1))

#define CP16(dst, src) \
    asm volatile("cp.async.cg.shared.global [%0], [%1], 16;" :: "r"(dst), "l"(src))
#define CP_COMMIT() asm volatile("cp.async.commit_group;")
#define CP_WAIT0()  asm volatile("cp.async.wait_group 0;")

// ---------------- prep kernels ----------------------------------------------
__global__ void init_scales_kernel() {
    if (threadIdx.x < 8) g_scaleB[threadIdx.x] = 0.f;
}

__global__ void pad_input_kernel(const float* __restrict__ x,
                                 float* __restrict__ pA, float* __restrict__ pB) {
    __shared__ float red[256];
    int i = blockIdx.x * 256 + threadIdx.x;
    float m = 0.f;
    if (i < 4734976) {
        int plane = i / PHW, rem = i - plane * PHW;
        int h = rem / PW - 2, w = rem % PW - 2;
        float v = 0.f;
        if (h >= 0 && h < 64 && w >= 0 && w < 64) v = x[plane * HWSZ + h * 64 + w];
        pA[i] = v;
        pB[i] = 0.f;
        m = fabsf(v);
    }
    red[threadIdx.x] = m;
    __syncthreads();
    for (int s = 128; s; s >>= 1) {
        if (threadIdx.x < s) red[threadIdx.x] = fmaxf(red[threadIdx.x], red[threadIdx.x + s]);
        __syncthreads();
    }
    if (threadIdx.x == 0)
        atomicMax((unsigned int*)&g_scaleB[0], __float_as_uint(red[0]));
}

// per-(r,oc) row quantization of main weights
__global__ void prep_w8_kernel(const float* __restrict__ w,
                               int8_t* __restrict__ wh, int8_t* __restrict__ wl,
                               float* __restrict__ sa) {
    __shared__ float red[256];
    int blk = blockIdx.x;          // r*256 + oc
    int r = blk >> 8;
    const float* wrow = w + (size_t)blk * 2304;
    float m = 0.f;
    for (int i = threadIdx.x; i < 2304; i += 256) m = fmaxf(m, fabsf(wrow[i]));
    red[threadIdx.x] = m;
    __syncthreads();
    for (int s = 128; s; s >>= 1) {
        if (threadIdx.x < s) red[threadIdx.x] = fmaxf(red[threadIdx.x], red[threadIdx.x + s]);
        __syncthreads();
    }
    float rm = fmaxf(red[0], 1e-20f);
    if (threadIdx.x == 0) sa[blk] = rm * (1.0f / 127.0f);
    float inv = 127.0f / rm;
    int oc = blk & 255;
    for (int i = threadIdx.x; i < 2304; i += 256) {
        int c = i / 9, kk = i - c * 9;
        float q = wrow[i] * inv;
        float hf = rintf(q);
        int hi = (int)hf;
        int lo = __float2int_rn((q - hf) * 128.f);
        int kb = kk * 2 + (c >> 7), j = c & 127;
        size_t dst = (((size_t)r * 18 + kb) * 256 + oc) * 128 + j;
        wh[dst] = (int8_t)hi;
        wl[dst] = (int8_t)lo;
    }
}

__global__ void prep_offw_kernel(const float* __restrict__ offw,
                                 __nv_bfloat16* __restrict__ owhi,
                                 __nv_bfloat16* __restrict__ owlo) {
    int idx = blockIdx.x * 256 + threadIdx.x;
    if (idx >= 294912) return;
    int r = idx / 73728;
    int rem = idx - r * 73728;
    int kb = rem >> 11;
    int rem2 = rem & 2047;
    int ocp = rem2 >> 6;
    int j = rem2 & 63;
    int kk = kb >> 2;
    int c = ((kb & 3) << 6) + j;
    float v = (ocp < OC2) ? offw[((r * OC2 + ocp) * 256 + c) * 9 + kk] : 0.f;
    __nv_bfloat16 h = __float2bfloat16_rn(v);
    owhi[idx] = h;
    owlo[idx] = __float2bfloat16_rn(v - __bfloat162float(h));
}

// ---------------- helpers ----------------------------------------------------
static __device__ __forceinline__ void cvt_pair(float v0, float v1,
        uint32_t& hp, uint32_t& lp) {
    __nv_bfloat162 h2, l2;
    h2.x = __float2bfloat16_rn(v0);
    h2.y = __float2bfloat16_rn(v1);
    l2.x = __float2bfloat16_rn(v0 - __bfloat162float(h2.x));
    l2.y = __float2bfloat16_rn(v1 - __bfloat162float(h2.y));
    hp = *(uint32_t*)&h2;
    lp = *(uint32_t*)&l2;
}

// ---------------- fused layer kernel ----------------------------------------
// grid = 256 CTAs (4 b x 64 row-tiles of 64 px), 512 threads / 16 warps.
// Phase1: bf16 offset GEMM 32x64. Phase2: int8 deform GEMM 256oc x 64px,
// warp tile 32x32, dual s32 accumulators (hh + mixed/128).
__global__ __launch_bounds__(512, 1) void fused_layer_kernel(
    const float* __restrict__ xpad,
    const __nv_bfloat16* __restrict__ owhi, const __nv_bfloat16* __restrict__ owlo,
    const float* __restrict__ offbias,
    const int8_t* __restrict__ wh8, const int8_t* __restrict__ wl8,
    const float* __restrict__ sa_base, float* scaleB, int r,
    float* __restrict__ outp, int pad_out)
{
    extern __shared__ char smem[];
    uint32_t sb = smem_u32(smem);
    int tid = threadIdx.x;
    int lane = tid & 31;
    int wid = tid >> 5;
    int b = blockIdx.x >> 6;
    int px0 = (blockIdx.x & 63) << 6;    // one image row per CTA

    int px = tid & 63;
    int cg = tid >> 6;                   // 0..7
    int hpx = (px0 + px) >> 6;
    int wpx = (px0 + px) & 63;

    if (tid < 256) ((float*)(smem + SM_SA))[tid] = sa_base[tid];

    // ================= PHASE 1: bf16 offset conv GEMM (D_off[32][64]) ======
    float acc1[4] = {0.f, 0.f, 0.f, 0.f};
    int mh = wid & 1;                    // m16 half
    int ng = wid >> 1;                   // n8 group (0..7)

    for (int kb = 0; kb < 36; ++kb) {
        int kk = kb >> 2;
        if (kb) __syncthreads();

        // stage A_off hi/lo (32x64 bf16, 4KB each)
        if (tid < 256) {
            int row = tid >> 3, seg = tid & 7;
            uint32_t o = SW(row, seg << 4);
            *(uint4*)(smem + SM_A + o) =
                ((const uint4*)(owhi + ((size_t)kb << 11)))[tid];
            *(uint4*)(smem + SM_ALO + o) =
                ((const uint4*)(owlo + ((size_t)kb << 11)))[tid];
        }
        // stage B im2col bf16: [64px][64ck], thread: 8 channels
        {
            const float* xb = xpad + ((size_t)(b * 256) + ((kb & 3) << 6) + (cg << 3)) * PHW
                            + (hpx + kk / 3 + 1) * PW + (wpx + kk % 3 + 1);
            uint32_t hp[4], lp[4];
#pragma unroll
            for (int jj = 0; jj < 4; ++jj) {
                float v0 = xb[(size_t)(jj * 2) * PHW];
                float v1 = xb[(size_t)(jj * 2 + 1) * PHW];
                cvt_pair(v0, v1, hp[jj], lp[jj]);
            }
            uint32_t o = SW(px, cg << 4);
            *(uint4*)(smem + SM_B + o) = make_uint4(hp[0], hp[1], hp[2], hp[3]);
            *(uint4*)(smem + SM_BLO + o) = make_uint4(lp[0], lp[1], lp[2], lp[3]);
        }
        __syncthreads();

#pragma unroll
        for (int ks = 0; ks < 4; ++ks) {
            uint32_t a1[4], bh1[2], bl1[2];
            int brow = (ng << 3) + (lane & 7);
            uint32_t bo = SW(brow, (ks << 5) + (((lane >> 3) & 1) << 4));
            LDSM2(bh1, sb + SM_B + bo);
            LDSM2(bl1, sb + SM_BLO + bo);
            int arow = (mh << 4) + (lane & 15);
            uint32_t ao = SW(arow, (ks << 5) + ((lane >> 4) << 4));
            LDSM4(a1, sb + SM_ALO + ao);
            MMA16816(acc1, a1, bh1[0], bh1[1]);
            LDSM4(a1, sb + SM_A + ao);
            MMA16816(acc1, a1, bh1[0], bh1[1]);
            MMA16816(acc1, a1, bl1[0], bl1[1]);
        }
    }
    __syncthreads();

    // offsets to smem (reuse SM_B): offs[32][64] f32
    {
        float* offs = (float*)(smem + SM_B);
        int ocp = (mh << 4) + (lane >> 2);
        int pc = (ng << 3) + ((lane & 3) << 1);
        offs[ocp * 64 + pc] = acc1[0];
        offs[ocp * 64 + pc + 1] = acc1[1];
        offs[(ocp + 8) * 64 + pc] = acc1[2];
        offs[(ocp + 8) * 64 + pc + 1] = acc1[3];
    }
    __syncthreads();

    // bilinear metadata: 9 taps x 64 px
    {
        const float* offs = (const float*)(smem + SM_B);
        int* sIdx = (int*)(smem + SM_IDX);
        float* sWy = (float*)(smem + SM_WY);
        float* sWx = (float*)(smem + SM_WX);
        for (int i = tid; i < 576; i += 512) {
            int kk = i >> 6;
            int p = i & 63;
            int pix = px0 + p;
            int h = pix >> 6;
            int w = pix & 63;
            float dy = offs[(2 * kk) * 64 + p] + offbias[2 * kk];
            float dx = offs[(2 * kk + 1) * 64 + p] + offbias[2 * kk + 1];
            float py = fminf(fmaxf((float)(h + kk / 3 - 1) + dy, -1.5f), 64.5f);
            float pxx = fminf(fmaxf((float)(w + kk % 3 - 1) + dx, -1.5f), 64.5f);
            float y0f = floorf(py), x0f = floorf(pxx);
            sIdx[i] = ((int)y0f + 2) * PW + ((int)x0f + 2);
            sWy[i] = py - y0f;
            sWx[i] = pxx - x0f;
        }
    }
    __syncthreads();

    // ================= PHASE 2: int8 deform GEMM (256oc x 64px) ===========
    float t = fmaxf(scaleB[r], 1e-20f);
    float inv = 127.0f / t;
    float tsc = t * (1.0f / 127.0f);

    int acch[2][4][4], accm[2][4][4];
#pragma unroll
    for (int mi = 0; mi < 2; ++mi)
#pragma unroll
        for (int nj = 0; nj < 4; ++nj)
#pragma unroll
            for (int q = 0; q < 4; ++q) { acch[mi][nj][q] = 0; accm[mi][nj][q] = 0; }

    int m_base = (wid & 7) << 5;       // 0..224
    int n_base = (wid >> 3) << 5;      // 0 or 32

    for (int kb = 0; kb < 18; ++kb) {
        int kk = kb >> 1;
        int c0 = (kb & 1) << 7;
        __syncthreads();

        // stage A s8 hi/lo via cp.async: 256 rows x 128 B each (4 chunks/thread)
        {
            const char* ah = (const char*)wh8 + ((size_t)kb << 15);
            const char* al = (const char*)wl8 + ((size_t)kb << 15);
#pragma unroll
            for (int tt = 0; tt < 4; ++tt) {
                int i = tid + (tt << 9);
                int row = i >> 3, seg = i & 7;
                uint32_t o = SW(row, seg << 4);
                CP16(sb + SM_A + o, ah + ((size_t)i << 4));
                CP16(sb + SM_ALO + o, al + ((size_t)i << 4));
            }
            CP_COMMIT();
        }

        // stage B: gather + interp + quantize, 16 channels per thread
        {
            int mi_ = kk * 64 + px;
            int idx0 = ((const int*)(smem + SM_IDX))[mi_];
            float wy = ((const float*)(smem + SM_WY))[mi_];
            float wx = ((const float*)(smem + SM_WX))[mi_];
            float w01 = (1.f - wy) * wx;
            float w00 = (1.f - wy) - w01;
            float w11 = wy * wx;
            float w10 = wy - w11;
            const float* xb = xpad + ((size_t)(b * 256) + c0 + (cg << 4)) * PHW + idx0;
            uint32_t hw4[4], lw4[4];
#pragma unroll
            for (int g = 0; g < 4; ++g) {
                uint32_t hp = 0, lp = 0;
#pragma unroll
                for (int u = 0; u < 4; ++u) {
                    const float* p0 = xb + (size_t)(g * 4 + u) * PHW;
                    float v = fmaf(w11, p0[PW + 1], fmaf(w10, p0[PW],
                              fmaf(w01, p0[1], w00 * p0[0])));
                    float q = v * inv;
                    float hf = rintf(q);
                    int hi = (int)hf;
                    int lo = __float2int_rn((q - hf) * 128.f);
                    hp |= (uint32_t)(hi & 255) << (u * 8);
                    lp |= (uint32_t)(lo & 255) << (u * 8);
                }
                hw4[g] = hp;
                lw4[g] = lp;
            }
            uint32_t o = SW(px, cg << 4);
            *(uint4*)(smem + SM_B + o) = make_uint4(hw4[0], hw4[1], hw4[2], hw4[3]);
            *(uint4*)(smem + SM_BLO + o) = make_uint4(lw4[0], lw4[1], lw4[2], lw4[3]);
        }
        CP_WAIT0();
        __syncthreads();

        // mma: 4 k32-steps, warp tile 32x32
#pragma unroll
        for (int ks = 0; ks < 4; ++ks) {
            uint32_t bh[2][4], a2[2][4];
            int brow0 = n_base + ((lane >> 4) << 3) + (lane & 7);
            uint32_t bcolb = (uint32_t)((ks << 5) + (((lane >> 3) & 1) << 4));
            int arow0 = m_base + (lane & 15);
            uint32_t acolb = (uint32_t)((ks << 5) + ((lane >> 4) << 4));
            LDSM4(bh[0], sb + SM_B + SW(brow0, bcolb));
            LDSM4(bh[1], sb + SM_B + SW(brow0 + 16, bcolb));
            LDSM4(a2[0], sb + SM_ALO + SW(arow0, acolb));
            LDSM4(a2[1], sb + SM_ALO + SW(arow0 + 16, acolb));
#pragma unroll
            for (int mi = 0; mi < 2; ++mi)
#pragma unroll
                for (int nj = 0; nj < 4; ++nj)
                    IMMA16832(accm[mi][nj], a2[mi], bh[nj >> 1][(nj & 1) * 2],
                              bh[nj >> 1][(nj & 1) * 2 + 1]);
            LDSM4(a2[0], sb + SM_A + SW(arow0, acolb));
            LDSM4(a2[1], sb + SM_A + SW(arow0 + 16, acolb));
#pragma unroll
            for (int mi = 0; mi < 2; ++mi)
#pragma unroll
                for (int nj = 0; nj < 4; ++nj)
                    IMMA16832(acch[mi][nj], a2[mi], bh[nj >> 1][(nj & 1) * 2],
                              bh[nj >> 1][(nj & 1) * 2 + 1]);
            LDSM4(bh[0], sb + SM_BLO + SW(brow0, bcolb));
            LDSM4(bh[1], sb + SM_BLO + SW(brow0 + 16, bcolb));
#pragma unroll
            for (int mi = 0; mi < 2; ++mi)
#pragma unroll
                for (int nj = 0; nj < 4; ++nj)
                    IMMA16832(accm[mi][nj], a2[mi], bh[nj >> 1][(nj & 1) * 2],
                              bh[nj >> 1][(nj & 1) * 2 + 1]);
        }
    }

    // ---- epilogue: dequant + relu + stores + next-layer scale ----
    float mloc = 0.f;
    int plane = pad_out ? PHW : HWSZ;
    int ostride = pad_out ? PW : 64;
    int obase = pad_out ? PBASE : 0;
    const float* ssa = (const float*)(smem + SM_SA);
#pragma unroll
    for (int mi = 0; mi < 2; ++mi) {
#pragma unroll
        for (int nj = 0; nj < 4; ++nj) {
            int row = m_base + (mi << 4) + (lane >> 2);
            int colp = n_base + (nj << 3) + ((lane & 3) << 1);
            int pix = px0 + colp;
            int h = pix >> 6;
            int wv = pix & 63;
            float s0 = ssa[row] * tsc;
            float s1 = ssa[row + 8] * tsc;
            float f0 = s0 * ((float)acch[mi][nj][0] + (float)accm[mi][nj][0] * 0.0078125f);
            float f1 = s0 * ((float)acch[mi][nj][1] + (float)accm[mi][nj][1] * 0.0078125f);
            float f2 = s1 * ((float)acch[mi][nj][2] + (float)accm[mi][nj][2] * 0.0078125f);
            float f3 = s1 * ((float)acch[mi][nj][3] + (float)accm[mi][nj][3] * 0.0078125f);
            f0 = fmaxf(f0, 0.f); f1 = fmaxf(f1, 0.f);
            f2 = fmaxf(f2, 0.f); f3 = fmaxf(f3, 0.f);
            mloc = fmaxf(mloc, fmaxf(fmaxf(f0, f1), fmaxf(f2, f3)));
            float* d0 = outp + (size_t)(b * 256 + row) * plane + h * ostride + wv + obase;
            float* d1 = outp + (size_t)(b * 256 + row + 8) * plane + h * ostride + wv + obase;
            *(float2*)d0 = make_float2(f0, f1);
            *(float2*)d1 = make_float2(f2, f3);
        }
    }

    // propagate activation max to next layer's scale
    __syncthreads();
#pragma unroll
    for (int off = 16; off; off >>= 1)
        mloc = fmaxf(mloc, __shfl_xor_sync(0xFFFFFFFFu, mloc, off));
    float* red = (float*)(smem + SM_IDX);
    if (lane == 0) red[wid] = mloc;
    __syncthreads();
    if (tid == 0) {
        float m = red[0];
#pragma unroll
        for (int i = 1; i < 16; ++i) m = fmaxf(m, red[i]);
        atomicMax((unsigned int*)&scaleB[r + 1], __float_as_uint(m));
    }
}

// ---------------- launch ----------------------------------------------------
extern "C" void kernel_launch(void* const* d_in, const int* in_sizes, int n_in,
                              void* d_out, int out_size) {
    (void)in_sizes; (void)n_in; (void)out_size;
    const float* x    = (const float*)d_in[0];
    const float* offw = (const float*)d_in[1];
    const float* offb = (const float*)d_in[2];
    const float* w    = (const float*)d_in[3];
    float* out = (float*)d_out;

    float *padA, *padB, *sa, *scB;
    int8_t *wh8, *wl8;
    __nv_bfloat16 *gowhi, *gowlo;
    cudaGetSymbolAddress((void**)&padA, g_padA);
    cudaGetSymbolAddress((void**)&padB, g_padB);
    cudaGetSymbolAddress((void**)&wh8, g_wh8);
    cudaGetSymbolAddress((void**)&wl8, g_wl8);
    cudaGetSymbolAddress((void**)&sa, g_sa);
    cudaGetSymbolAddress((void**)&scB, g_scaleB);
    cudaGetSymbolAddress((void**)&gowhi, g_owhi);
    cudaGetSymbolAddress((void**)&gowlo, g_owlo);

    cudaFuncSetAttribute(fused_layer_kernel,
                         cudaFuncAttributeMaxDynamicSharedMemorySize, SM_TOTAL);

    init_scales_kernel<<<1, 32>>>();
    pad_input_kernel<<<(4734976 + 255) / 256, 256>>>(x, padA, padB);
    prep_w8_kernel<<<1024, 256>>>(w, wh8, wl8, sa);
    prep_offw_kernel<<<(294912 + 255) / 256, 256>>>(offw, gowhi, gowlo);

    const float* cur = padA;
    for (int r = 0; r < RB; ++r) {
        int last = (r == 3);
        float* nxt = last ? out : ((r & 1) == 0 ? padB : padA);
        fused_layer_kernel<<<256, 512, SM_TOTAL>>>(
            cur, gowhi + (size_t)r * 73728, gowlo + (size_t)r * 73728,
            offb + r * OC2,
            wh8 + (size_t)r * 589824, wl8 + (size_t)r * 589824,
            sa + r * 256, scB, r, nxt, last ? 0 : 1);
        cur = nxt;
    }
}

// round 14
// speedup vs baseline: 2.4854x; 2.3294x over previous
#include <cuda_runtime.h>
#include <cuda_bf16.h>
#include <math.h>
#include <stdint.h>

#define RB 4
#define CC 256
#define HWSZ 4096
#define OC2 18
#define PW 68
#define PHW 4624            // 68*68
#define PBASE 138           // 2*68 + 2

// ---------------- smem layout (bytes, dynamic) ------------------------------
#define SM_A    0           // A hi: phase2 256x64 bf16 = 32KB; phase1 32x64 = 4KB
#define SM_ALO  32768       // A lo
#define SM_BHI  65536       // B hi 128px x 64ck bf16 = 16KB (phase1 offs f32 reuses)
#define SM_BLO  81920       // B lo
#define SM_IDX  98304       // int[1152]
#define SM_WY   102912      // float[1152]
#define SM_WX   107520      // float[1152]
#define SM_TOTAL 112128

// 128B-row swizzle (R5-proven)
#define SW(row, colb) (((uint32_t)(row) << 7) + \
    ((uint32_t)(colb) ^ (((uint32_t)(row) & 7) << 4)))

// ---------------- scratch ----------------------------------------------------
__device__ float g_padA[4734976];    // 4*256*68*68 padded planes
__device__ float g_padB[4734976];
// main weights: [r][kb=kk*4+cb (36)][oc (256)][j (64)], c = cb*64+j
__device__ __align__(16) __nv_bfloat16 g_whi[2359296];
__device__ __align__(16) __nv_bfloat16 g_wlo[2359296];
// offset weights: [r][kb (36)][ocp (32)][j (64)]
__device__ __align__(16) __nv_bfloat16 g_owhi[294912];
__device__ __align__(16) __nv_bfloat16 g_owlo[294912];

// ---------------- PTX helpers ----------------------------------------------
static __device__ __forceinline__ uint32_t smem_u32(const void* p) {
    uint32_t a;
    asm("{ .reg .u64 t; cvta.to.shared.u64 t, %1; cvt.u32.u64 %0, t; }" : "=r"(a) : "l"(p));
    return a;
}

#define LDSM4(r, a) \
    asm volatile("ldmatrix.sync.aligned.m8n8.x4.shared.b16 {%0,%1,%2,%3}, [%4];" \
                 : "=r"((r)[0]), "=r"((r)[1]), "=r"((r)[2]), "=r"((r)[3]) : "r"(a))

#define LDSM2(r, a) \
    asm volatile("ldmatrix.sync.aligned.m8n8.x2.shared.b16 {%0,%1}, [%2];" \
                 : "=r"((r)[0]), "=r"((r)[1]) : "r"(a))

#define MMA16816(c, a, b0, b1) \
    asm volatile("mma.sync.aligned.m16n8k16.row.col.f32.bf16.bf16.f32 " \
                 "{%0,%1,%2,%3}, {%4,%5,%6,%7}, {%8,%9}, {%0,%1,%2,%3};" \
                 : "+f"((c)[0]), "+f"((c)[1]), "+f"((c)[2]), "+f"((c)[3]) \
                 : "r"((a)[0]), "r"((a)[1]), "r"((a)[2]), "r"((a)[3]), \
                   "r"(b0), "r"(b1))

// ---------------- prep kernels ----------------------------------------------
__global__ void pad_input_kernel(const float* __restrict__ x,
                                 float* __restrict__ pA, float* __restrict__ pB) {
    int i = blockIdx.x * 256 + threadIdx.x;
    if (i >= 4734976) return;
    int plane = i / PHW, rem = i - plane * PHW;
    int h = rem / PW - 2, w = rem % PW - 2;
    float v = 0.f;
    if (h >= 0 && h < 64 && w >= 0 && w < 64) v = x[plane * HWSZ + h * 64 + w];
    pA[i] = v;
    pB[i] = 0.f;
}

__global__ void prep_w_kernel(const float* __restrict__ w,
                              __nv_bfloat16* __restrict__ whi,
                              __nv_bfloat16* __restrict__ wlo) {
    int idx = blockIdx.x * 256 + threadIdx.x;
    if (idx >= 2359296) return;
    int r = idx / 589824;
    int rem = idx - r * 589824;
    int kb = rem >> 14;
    int rem2 = rem & 16383;
    int oc = rem2 >> 6;
    int j = rem2 & 63;
    int kk = kb >> 2;
    int c = ((kb & 3) << 6) + j;
    float v = w[(((r * 256 + oc) * 256 + c) * 9) + kk];
    __nv_bfloat16 h = __float2bfloat16_rn(v);
    whi[idx] = h;
    wlo[idx] = __float2bfloat16_rn(v - __bfloat162float(h));
}

__global__ void prep_offw_kernel(const float* __restrict__ offw,
                                 __nv_bfloat16* __restrict__ owhi,
                                 __nv_bfloat16* __restrict__ owlo) {
    int idx = blockIdx.x * 256 + threadIdx.x;
    if (idx >= 294912) return;
    int r = idx / 73728;
    int rem = idx - r * 73728;
    int kb = rem >> 11;
    int rem2 = rem & 2047;
    int ocp = rem2 >> 6;
    int j = rem2 & 63;
    int kk = kb >> 2;
    int c = ((kb & 3) << 6) + j;
    float v = (ocp < OC2) ? offw[((r * OC2 + ocp) * 256 + c) * 9 + kk] : 0.f;
    __nv_bfloat16 h = __float2bfloat16_rn(v);
    owhi[idx] = h;
    owlo[idx] = __float2bfloat16_rn(v - __bfloat162float(h));
}

// ---------------- helpers ----------------------------------------------------
static __device__ __forceinline__ void cvt_pair(float v0, float v1,
        uint32_t& hp, uint32_t& lp) {
    __nv_bfloat162 h2, l2;
    h2.x = __float2bfloat16_rn(v0);
    h2.y = __float2bfloat16_rn(v1);
    l2.x = __float2bfloat16_rn(v0 - __bfloat162float(h2.x));
    l2.y = __float2bfloat16_rn(v1 - __bfloat162float(h2.y));
    hp = *(uint32_t*)&h2;
    lp = *(uint32_t*)&l2;
}

// ---------------- fused layer kernel (R5 structure + padded planes) ---------
// grid = 128 CTAs (4 batches x 32 px-tiles of 128), 512 threads / 16 warps.
__global__ __launch_bounds__(512, 1) void fused_layer_kernel(
    const float* __restrict__ xpad,
    const __nv_bfloat16* __restrict__ owhi, const __nv_bfloat16* __restrict__ owlo,
    const float* __restrict__ offbias,
    const __nv_bfloat16* __restrict__ whi, const __nv_bfloat16* __restrict__ wlo,
    float* __restrict__ outp, int pad_out)
{
    extern __shared__ char smem[];
    uint32_t sb = smem_u32(smem);
    int tid = threadIdx.x;
    int lane = tid & 31;
    int wid = tid >> 5;
    int b = blockIdx.x >> 5;
    int px0 = (blockIdx.x & 31) << 7;

    int px = tid & 127;
    int cg = tid >> 7;           // 0..3: 16-channel group
    int hpx = (px0 + px) >> 6;
    int wpx = (px0 + px) & 63;

    // ================= PHASE 1: offset conv GEMM (D_off[32][128]) ==========
    float acc1[2][4];
#pragma unroll
    for (int mi = 0; mi < 2; ++mi)
#pragma unroll
        for (int q = 0; q < 4; ++q) acc1[mi][q] = 0.f;

    for (int kb = 0; kb < 36; ++kb) {
        int kk = kb >> 2;
        if (kb) __syncthreads();

        // stage A_off hi/lo: 32 rows x 64 ck (4KB each)
        if (tid < 256) {
            int row = tid >> 3, seg = tid & 7;
            uint32_t o = SW(row, seg << 4);
            *(uint4*)(smem + SM_A + o) =
                ((const uint4*)(owhi + ((size_t)kb << 11)))[tid];
            *(uint4*)(smem + SM_ALO + o) =
                ((const uint4*)(owlo + ((size_t)kb << 11)))[tid];
        }

        // stage B im2col: [128 px][64 ck], padded planes (no predicates)
        {
            const float* xb = xpad + ((size_t)(b * 256) + ((kb & 3) << 6) + (cg << 4)) * PHW
                            + (hpx + kk / 3 + 1) * PW + (wpx + kk % 3 + 1);
            uint32_t hp[8], lp[8];
#pragma unroll
            for (int jj = 0; jj < 8; ++jj) {
                float v0 = xb[(size_t)(jj << 1) * PHW];
                float v1 = xb[(size_t)((jj << 1) + 1) * PHW];
                cvt_pair(v0, v1, hp[jj], lp[jj]);
            }
            uint32_t o0 = SW(px, cg << 5);
            uint32_t o1 = SW(px, (cg << 5) + 16);
            *(uint4*)(smem + SM_BHI + o0) = make_uint4(hp[0], hp[1], hp[2], hp[3]);
            *(uint4*)(smem + SM_BHI + o1) = make_uint4(hp[4], hp[5], hp[6], hp[7]);
            *(uint4*)(smem + SM_BLO + o0) = make_uint4(lp[0], lp[1], lp[2], lp[3]);
            *(uint4*)(smem + SM_BLO + o1) = make_uint4(lp[4], lp[5], lp[6], lp[7]);
        }
        __syncthreads();

        // mma: warp wid covers n8 col = wid*8, two m16 halves
        int n_base = wid << 3;
#pragma unroll
        for (int ks = 0; ks < 4; ++ks) {
            uint32_t ah1[2][4], al1[2][4], bh1[2], bl1[2];
#pragma unroll
            for (int mi = 0; mi < 2; ++mi) {
                int row = (mi << 4) + (lane & 15);
                uint32_t o = SW(row, (ks << 5) + ((lane >> 4) << 4));
                LDSM4(ah1[mi], sb + SM_A + o);
                LDSM4(al1[mi], sb + SM_ALO + o);
            }
            int brow = n_base + (lane & 7);
            uint32_t bo = SW(brow, (ks << 5) + (((lane >> 3) & 1) << 4));
            LDSM2(bh1, sb + SM_BHI + bo);
            LDSM2(bl1, sb + SM_BLO + bo);
#pragma unroll
            for (int mi = 0; mi < 2; ++mi) {
                MMA16816(acc1[mi], ah1[mi], bh1[0], bh1[1]);
                MMA16816(acc1[mi], al1[mi], bh1[0], bh1[1]);
                MMA16816(acc1[mi], ah1[mi], bl1[0], bl1[1]);
            }
        }
    }
    __syncthreads();

    // write offsets to smem (reuse SM_BHI region): offs[32][128] f32
    {
        float* offs = (float*)(smem + SM_BHI);
#pragma unroll
        for (int mi = 0; mi < 2; ++mi) {
            int ocp = (mi << 4) + (lane >> 2);
            int pc = (wid << 3) + ((lane & 3) << 1);
            offs[ocp * 128 + pc] = acc1[mi][0];
            offs[ocp * 128 + pc + 1] = acc1[mi][1];
            offs[(ocp + 8) * 128 + pc] = acc1[mi][2];
            offs[(ocp + 8) * 128 + pc + 1] = acc1[mi][3];
        }
    }
    __syncthreads();

    // ---- bilinear metadata (padded addressing, clamped) ----
    {
        const float* offs = (const float*)(smem + SM_BHI);
        int* sIdx = (int*)(smem + SM_IDX);
        float* sWy = (float*)(smem + SM_WY);
        float* sWx = (float*)(smem + SM_WX);
        for (int i = tid; i < 1152; i += 512) {
            int kk = i >> 7;
            int p = i & 127;
            int pix = px0 + p;
            int h = pix >> 6;
            int w = pix & 63;
            float dy = offs[((2 * kk) << 7) + p] + offbias[2 * kk];
            float dx = offs[((2 * kk + 1) << 7) + p] + offbias[2 * kk + 1];
            float py = fminf(fmaxf((float)(h + kk / 3 - 1) + dy, -1.5f), 64.5f);
            float pxx = fminf(fmaxf((float)(w + kk % 3 - 1) + dx, -1.5f), 64.5f);
            float y0f = floorf(py), x0f = floorf(pxx);
            sIdx[i] = ((int)y0f + 2) * PW + ((int)x0f + 2);
            sWy[i] = py - y0f;
            sWx[i] = pxx - x0f;
        }
    }
    __syncthreads();

    // ================= PHASE 2: deform GEMM (D[256][128]) ==================
    float acc[4][4][4];
#pragma unroll
    for (int mi = 0; mi < 4; ++mi)
#pragma unroll
        for (int nj = 0; nj < 4; ++nj)
#pragma unroll
            for (int q = 0; q < 4; ++q) acc[mi][nj][q] = 0.f;

    int m_base = (wid & 3) << 6;
    int n_base = (wid >> 2) << 5;

    for (int kb = 0; kb < 36; ++kb) {
        int kk = kb >> 2;
        if (kb) __syncthreads();

        // stage A (weights) hi/lo: [256 oc][64 ck] swizzled
        {
            const uint4* ah = (const uint4*)(whi + ((size_t)kb << 14));
            const uint4* al = (const uint4*)(wlo + ((size_t)kb << 14));
#pragma unroll
            for (int t = 0; t < 4; ++t) {
                int i = tid + (t << 9);
                int row = i >> 3, seg = i & 7;
                uint32_t o = SW(row, seg << 4);
                *(uint4*)(smem + SM_A + o) = ah[i];
                *(uint4*)(smem + SM_ALO + o) = al[i];
            }
        }

        // sample B tile: [128 px][64 ck] tap kk, padded planes, 16 ch/thread
        {
            int mi_ = kk * 128 + px;
            int idx0 = ((const int*)(smem + SM_IDX))[mi_];
            float wy = ((const float*)(smem + SM_WY))[mi_];
            float wx = ((const float*)(smem + SM_WX))[mi_];
            float w01 = (1.f - wy) * wx;
            float w00 = (1.f - wy) - w01;
            float w11 = wy * wx;
            float w10 = wy - w11;
            const float* xb = xpad + ((size_t)(b * 256) + ((kb & 3) << 6) + (cg << 4)) * PHW + idx0;
            uint32_t hp[8], lp[8];
#pragma unroll
            for (int jj = 0; jj < 8; ++jj) {
                const float* p0 = xb + (size_t)(jj << 1) * PHW;
                const float* p1 = p0 + PHW;
                float v0 = fmaf(w11, p0[PW + 1], fmaf(w10, p0[PW], fmaf(w01, p0[1], w00 * p0[0])));
                float v1 = fmaf(w11, p1[PW + 1], fmaf(w10, p1[PW], fmaf(w01, p1[1], w00 * p1[0])));
                cvt_pair(v0, v1, hp[jj], lp[jj]);
            }
            uint32_t o0 = SW(px, cg << 5);
            uint32_t o1 = SW(px, (cg << 5) + 16);
            *(uint4*)(smem + SM_BHI + o0) = make_uint4(hp[0], hp[1], hp[2], hp[3]);
            *(uint4*)(smem + SM_BHI + o1) = make_uint4(hp[4], hp[5], hp[6], hp[7]);
            *(uint4*)(smem + SM_BLO + o0) = make_uint4(lp[0], lp[1], lp[2], lp[3]);
            *(uint4*)(smem + SM_BLO + o1) = make_uint4(lp[4], lp[5], lp[6], lp[7]);
        }
        __syncthreads();

        // ldmatrix + mma: 4 k16-steps (R5 ordering)
#pragma unroll
        for (int ks = 0; ks < 4; ++ks) {
            uint32_t ah_[4][4], al_[4][4], bf[2][4];
            int arow0 = m_base + (lane & 15);
            uint32_t acolb = (uint32_t)((ks << 5) + ((lane >> 4) << 4));
#pragma unroll
            for (int mi = 0; mi < 4; ++mi) {
                int row = arow0 + (mi << 4);
                uint32_t o = SW(row, acolb);
                LDSM4(ah_[mi], sb + SM_A + o);
                LDSM4(al_[mi], sb + SM_ALO + o);
            }
            int brow0 = n_base + ((lane >> 4) << 3) + (lane & 7);
            uint32_t bcolb = (uint32_t)((ks << 5) + (((lane >> 3) & 1) << 4));
#pragma unroll
            for (int np = 0; np < 2; ++np) {
                int row = brow0 + (np << 4);
                LDSM4(bf[np], sb + SM_BHI + SW(row, bcolb));
            }
#pragma unroll
            for (int mi = 0; mi < 4; ++mi)
#pragma unroll
                for (int nj = 0; nj < 4; ++nj) {
                    MMA16816(acc[mi][nj], ah_[mi], bf[nj >> 1][(nj & 1) * 2], bf[nj >> 1][(nj & 1) * 2 + 1]);
                    MMA16816(acc[mi][nj], al_[mi], bf[nj >> 1][(nj & 1) * 2], bf[nj >> 1][(nj & 1) * 2 + 1]);
                }
#pragma unroll
            for (int np = 0; np < 2; ++np) {
                int row = brow0 + (np << 4);
                LDSM4(bf[np], sb + SM_BLO + SW(row, bcolb));
            }
#pragma unroll
            for (int mi = 0; mi < 4; ++mi)
#pragma unroll
                for (int nj = 0; nj < 4; ++nj)
                    MMA16816(acc[mi][nj], ah_[mi], bf[nj >> 1][(nj & 1) * 2], bf[nj >> 1][(nj & 1) * 2 + 1]);
        }
    }

    // ---- epilogue: relu + direct v2 stores (padded or flat output) ----
    int plane = pad_out ? PHW : HWSZ;
    int ostride = pad_out ? PW : 64;
    int obase = pad_out ? PBASE : 0;
#pragma unroll
    for (int mi = 0; mi < 4; ++mi) {
#pragma unroll
        for (int nj = 0; nj < 4; ++nj) {
            int row = m_base + (mi << 4) + (lane >> 2);
            int colp = n_base + (nj << 3) + ((lane & 3) << 1);
            int pix = px0 + colp;
            int h = pix >> 6;
            int wv = pix & 63;
            float* d0 = outp + (size_t)(b * 256 + row) * plane + h * ostride + wv + obase;
            float* d1 = outp + (size_t)(b * 256 + row + 8) * plane + h * ostride + wv + obase;
            float2 v0, v1;
            v0.x = fmaxf(acc[mi][nj][0], 0.f);
            v0.y = fmaxf(acc[mi][nj][1], 0.f);
            v1.x = fmaxf(acc[mi][nj][2], 0.f);
            v1.y = fmaxf(acc[mi][nj][3], 0.f);
            *(float2*)d0 = v0;
            *(float2*)d1 = v1;
        }
    }
}

// ---------------- launch ----------------------------------------------------
extern "C" void kernel_launch(void* const* d_in, const int* in_sizes, int n_in,
                              void* d_out, int out_size) {
    (void)in_sizes; (void)n_in; (void)out_size;
    const float* x    = (const float*)d_in[0];
    const float* offw = (const float*)d_in[1];
    const float* offb = (const float*)d_in[2];
    const float* w    = (const float*)d_in[3];
    float* out = (float*)d_out;

    float *padA, *padB;
    __nv_bfloat16 *gwhi, *gwlo, *gowhi, *gowlo;
    cudaGetSymbolAddress((void**)&padA, g_padA);
    cudaGetSymbolAddress((void**)&padB, g_padB);
    cudaGetSymbolAddress((void**)&gwhi, g_whi);
    cudaGetSymbolAddress((void**)&gwlo, g_wlo);
    cudaGetSymbolAddress((void**)&gowhi, g_owhi);
    cudaGetSymbolAddress((void**)&gowlo, g_owlo);

    cudaFuncSetAttribute(fused_layer_kernel,
                         cudaFuncAttributeMaxDynamicSharedMemorySize, SM_TOTAL);

    pad_input_kernel<<<(4734976 + 255) / 256, 256>>>(x, padA, padB);
    prep_w_kernel<<<(2359296 + 255) / 256, 256>>>(w, gwhi, gwlo);
    prep_offw_kernel<<<(294912 + 255) / 256, 256>>>(offw, gowhi, gowlo);

    const float* cur = padA;
    for (int r = 0; r < RB; ++r) {
        int last = (r == 3);
        float* nxt = last ? out : ((r & 1) == 0 ? padB : padA);
        fused_layer_kernel<<<128, 512, SM_TOTAL>>>(
            cur, gowhi + (size_t)r * 73728, gowlo + (size_t)r * 73728,
            offb + r * OC2, gwhi + (size_t)r * 589824, gwlo + (size_t)r * 589824,
            nxt, last ? 0 : 1);
        cur = nxt;
    }
}